// round 5
// baseline (speedup 1.0000x reference)
#include <cuda_runtime.h>
#include <math.h>

#define Bq 8
#define Sq 1024
#define Dq 1024
#define Fq 3584
#define Eq 2
#define NB 444
#define NT 256
#define EPSq 1e-6f

typedef unsigned long long ull;

// ---------------- device scratch (no allocation) ----------------
__device__ ull   g_pvu[64 * 4 * Dq];        // v0 partials [ic*4+p][j] (b-pairs)
__device__ float g_attn[Bq * Dq];           // attn output (atomic)
__device__ float g_accg[Eq * Bq * Fq];      // gate acc (atomic)
__device__ float g_accu[Eq * Bq * Fq];      // up acc (atomic)
__device__ float g_y[Bq * Dq];              // moe output (atomic)
__device__ unsigned g_barc = 0;
__device__ unsigned g_barg = 0;

// ---------------- f32x2 helpers ----------------
__device__ __forceinline__ ull pack2(float lo, float hi) {
    ull r;
    asm("mov.b64 %0, {%1, %2};" : "=l"(r) : "r"(__float_as_uint(lo)), "r"(__float_as_uint(hi)));
    return r;
}
__device__ __forceinline__ void unpack2(ull v, float& lo, float& hi) {
    unsigned a, b;
    asm("mov.b64 {%0, %1}, %2;" : "=r"(a), "=r"(b) : "l"(v));
    lo = __uint_as_float(a); hi = __uint_as_float(b);
}
#define FMA2(d, a, b) asm("fma.rn.f32x2 %0, %1, %2, %0;" : "+l"(d) : "l"(a), "l"(b))
#define ADD2(d, a)    asm("add.rn.f32x2 %0, %0, %1;"     : "+l"(d) : "l"(a))

// ---------------- software grid barrier ----------------
__device__ __forceinline__ void grid_bar() {
    __syncthreads();
    if (threadIdx.x == 0) {
        __threadfence();
        unsigned old = *(volatile unsigned*)&g_barg;
        if (atomicAdd(&g_barc, 1u) == (unsigned)gridDim.x - 1u) {
            g_barc = 0;
            __threadfence();
            atomicExch(&g_barg, old + 1u);
        } else {
            while (*(volatile unsigned*)&g_barg == old) __nanosleep(64);
        }
        __threadfence();
    }
    __syncthreads();
}

// ---------------- multi-value block reduction (8 warps) ----------
template <int NV>
__device__ __forceinline__ void breduce(const float* v, float* s_red, float* s_out) {
    int lane = threadIdx.x & 31, w = threadIdx.x >> 5;
#pragma unroll
    for (int k = 0; k < NV; k++) {
        float x = v[k];
#pragma unroll
        for (int o = 16; o; o >>= 1) x += __shfl_xor_sync(0xffffffffu, x, o);
        if (lane == 0) s_red[k * 8 + w] = x;
    }
    __syncthreads();
    if (threadIdx.x < NV) {
        float s = 0.f;
#pragma unroll
        for (int j = 0; j < 8; j++) s += s_red[threadIdx.x * 8 + j];
        s_out[threadIdx.x] = s;
    }
    __syncthreads();
}

__global__ void __launch_bounds__(NT, 3) fused_all(
    const float* __restrict__ hidden, const float* __restrict__ ln1w,
    const float* __restrict__ vw, const float* __restrict__ ow,
    const float* __restrict__ ln2w, const float* __restrict__ rw,
    const float* __restrict__ gw, const float* __restrict__ uw,
    const float* __restrict__ dw, const float* __restrict__ flnw,
    const float* __restrict__ sw, float* __restrict__ out)
{
    __shared__ float s_ht[Dq * Bq];   // 32KB: activation transposed [d][b] as b-pairs
    __shared__ float s_v[16 * Bq];    // v0 chunk in B; t-vector in D
    __shared__ float s_red[16 * 8];
    __shared__ float s_out[16];
    __shared__ float s_rs[Bq];
    __shared__ int   s_sel[Bq];
    __shared__ float s_tw[Bq];

    const int tid = threadIdx.x;
    const int blk = blockIdx.x;
    ull* s_htu = (ull*)s_ht;
    ull* s_vu  = (ull*)s_v;

    // ============ Stage A ============
    // A0: zero atomic accumulators
    for (int idx = blk * NT + tid; idx < Eq * Bq * Fq; idx += NB * NT) {
        g_accg[idx] = 0.f; g_accu[idx] = 0.f;
    }
    for (int idx = blk * NT + tid; idx < Bq * Dq; idx += NB * NT) {
        g_attn[idx] = 0.f; g_y[idx] = 0.f;
    }

    // A1: redundant per-block h1 = rmsnorm(x0)*ln1_w -> s_ht[d][b]
    {
        float ss[Bq];
#pragma unroll
        for (int b = 0; b < Bq; b++) ss[b] = 0.f;
#pragma unroll
        for (int it = 0; it < 4; it++) {
            int d = tid + it * 256;
#pragma unroll
            for (int b = 0; b < Bq; b++) {
                float v = hidden[(size_t)b * Sq * Dq + d];
                ss[b] += v * v;
            }
        }
        breduce<Bq>(ss, s_red, s_out);
        if (tid < Bq) s_rs[tid] = rsqrtf(s_out[tid] * (1.f / Dq) + EPSq);
        __syncthreads();
#pragma unroll
        for (int it = 0; it < 4; it++) {
            int d = tid + it * 256;
            float lw = ln1w[d];
#pragma unroll
            for (int b = 0; b < Bq; b++)
                s_ht[d * Bq + b] = hidden[(size_t)b * Sq * Dq + d] * s_rs[b] * lw;
        }
        __syncthreads();
    }

    // A2: v0 partials. 256 tasks: 64 i-chunks(16) x 4 j-chunks(256)
    if (blk < 256) {
        int ic = blk >> 2, jc = blk & 3;
        int j = jc * 256 + tid, ib = ic * 16;
        float w[16];
#pragma unroll
        for (int u = 0; u < 16; u++) w[u] = vw[(size_t)(ib + u) * Dq + j];
        ull acc[4] = {0, 0, 0, 0};
#pragma unroll
        for (int u = 0; u < 16; u++) {
            ull w2 = pack2(w[u], w[u]);
#pragma unroll
            for (int p = 0; p < 4; p++) FMA2(acc[p], s_htu[(ib + u) * 4 + p], w2);
        }
#pragma unroll
        for (int p = 0; p < 4; p++) g_pvu[(size_t)(ic * 4 + p) * Dq + j] = acc[p];
    }
    grid_bar();

    // ============ Stage B: attn = v0 @ o_w ============
    if (blk < 256) {
        int ic = blk >> 2, jc = blk & 3;
        int ib = ic * 16;
        if (tid < 64) {
            int i = tid >> 2, p = tid & 3;
            ull s = 0;
#pragma unroll 8
            for (int c = 0; c < 64; c++) {
                ull v = g_pvu[(size_t)(c * 4 + p) * Dq + ib + i];
                ADD2(s, v);
            }
            s_vu[i * 4 + p] = s;
        }
        __syncthreads();
        int j = jc * 256 + tid;
        float w[16];
#pragma unroll
        for (int u = 0; u < 16; u++) w[u] = ow[(size_t)(ib + u) * Dq + j];
        ull acc[4] = {0, 0, 0, 0};
#pragma unroll
        for (int u = 0; u < 16; u++) {
            ull w2 = pack2(w[u], w[u]);
#pragma unroll
            for (int p = 0; p < 4; p++) FMA2(acc[p], s_vu[u * 4 + p], w2);
        }
#pragma unroll
        for (int p = 0; p < 4; p++) {
            float lo, hi; unpack2(acc[p], lo, hi);
            atomicAdd(&g_attn[(2 * p) * Dq + j], lo);
            atomicAdd(&g_attn[(2 * p + 1) * Dq + j], hi);
        }
    }
    grid_bar();

    // ============ Stage C1: xmid -> h2 (s_ht transposed) + router ============
    {
        __syncthreads();
        float ss[Bq];
#pragma unroll
        for (int b = 0; b < Bq; b++) ss[b] = 0.f;
#pragma unroll
        for (int it = 0; it < 4; it++) {
            int d = tid + it * 256;
#pragma unroll
            for (int b = 0; b < Bq; b++) {
                float v = hidden[(size_t)b * Sq * Dq + d] + g_attn[b * Dq + d];
                ss[b] += v * v;
            }
        }
        breduce<Bq>(ss, s_red, s_out);
        if (tid < Bq) s_rs[tid] = rsqrtf(s_out[tid] * (1.f / Dq) + EPSq);
        __syncthreads();
        float l[16];
#pragma unroll
        for (int k = 0; k < 16; k++) l[k] = 0.f;
#pragma unroll
        for (int it = 0; it < 4; it++) {
            int d = tid + it * 256;
            float r0 = rw[d * 2 + 0], r1 = rw[d * 2 + 1], w2d = ln2w[d];
#pragma unroll
            for (int b = 0; b < Bq; b++) {
                float xm = hidden[(size_t)b * Sq * Dq + d] + g_attn[b * Dq + d];
                float h2 = xm * s_rs[b] * w2d;
                s_ht[d * Bq + b] = h2;
                l[b]     = fmaf(h2, r0, l[b]);
                l[8 + b] = fmaf(h2, r1, l[8 + b]);
            }
        }
        breduce<16>(l, s_red, s_out);
        if (tid < Bq) {
            float l0 = s_out[tid], l1 = s_out[8 + tid];
            s_sel[tid] = (l1 > l0) ? 1 : 0;
            s_tw[tid]  = 1.f / (1.f + expf(-fabsf(l0 - l1)));
        }
        __syncthreads();
    }

    bool usedE[Eq];
#pragma unroll
    for (int e = 0; e < Eq; e++) {
        bool u = false;
#pragma unroll
        for (int b = 0; b < Bq; b++) u |= (s_sel[b] == e);
        usedE[e] = u;
    }

    // ============ Stage C2: gate|up. 512 tasks: e x m x 32 ic(32) x 4 fc(896) ====
    for (int t = blk; t < 512; t += NB) {
        int fc = t & 3;
        int ic = (t >> 2) & 31;
        int m  = (t >> 7) & 1;
        int e  = (t >> 8) & 1;
        if (!usedE[e] || tid >= 224) continue;
        int f0 = fc * 896 + tid * 4;
        int ib = ic * 32;
        const float* wp = (m ? uw : gw) + (size_t)e * Dq * Fq + f0;
        ull acc[4][4];
#pragma unroll
        for (int q = 0; q < 4; q++)
#pragma unroll
            for (int p = 0; p < 4; p++) acc[q][p] = 0;
        for (int i4 = 0; i4 < 32; i4 += 4) {
            float4 w[4];
#pragma unroll
            for (int u = 0; u < 4; u++)
                w[u] = *(const float4*)(wp + (size_t)(ib + i4 + u) * Fq);
#pragma unroll
            for (int u = 0; u < 4; u++) {
                ull wx = pack2(w[u].x, w[u].x);
                ull wy = pack2(w[u].y, w[u].y);
                ull wz = pack2(w[u].z, w[u].z);
                ull ww = pack2(w[u].w, w[u].w);
#pragma unroll
                for (int p = 0; p < 4; p++) {
                    ull h2 = s_htu[(ib + i4 + u) * 4 + p];
                    FMA2(acc[0][p], h2, wx);
                    FMA2(acc[1][p], h2, wy);
                    FMA2(acc[2][p], h2, wz);
                    FMA2(acc[3][p], h2, ww);
                }
            }
        }
        float* dst = (m ? g_accu : g_accg) + (size_t)e * Bq * Fq;
#pragma unroll
        for (int q = 0; q < 4; q++)
#pragma unroll
            for (int p = 0; p < 4; p++) {
                float lo, hi; unpack2(acc[q][p], lo, hi);
                atomicAdd(&dst[(size_t)(2 * p) * Fq + f0 + q], lo);
                atomicAdd(&dst[(size_t)(2 * p + 1) * Fq + f0 + q], hi);
            }
    }
    grid_bar();

    // ============ Stage D: silu/mask + down. 448 tasks: e x 224 fc(16 rows) ====
    for (int t = blk; t < 448; t += NB) {
        int e = t / 224, fc = t % 224;
        if (usedE[e]) {
            int f0 = fc * 16;
            __syncthreads();   // previous iteration's s_vu reads done
            if (tid < 64) {
                int fl = tid >> 2, p = tid & 3;
                int f = f0 + fl;
                int b0 = 2 * p, b1 = 2 * p + 1;
                float t0 = 0.f, t1 = 0.f;
                if (s_sel[b0] == e) {
                    float gg = g_accg[((size_t)e * Bq + b0) * Fq + f];
                    float uu = g_accu[((size_t)e * Bq + b0) * Fq + f];
                    t0 = s_tw[b0] * gg * (1.f / (1.f + expf(-gg))) * uu;
                }
                if (s_sel[b1] == e) {
                    float gg = g_accg[((size_t)e * Bq + b1) * Fq + f];
                    float uu = g_accu[((size_t)e * Bq + b1) * Fq + f];
                    t1 = s_tw[b1] * gg * (1.f / (1.f + expf(-gg))) * uu;
                }
                s_vu[fl * 4 + p] = pack2(t0, t1);
            }
            __syncthreads();
            int d0 = tid * 4;
            const float* wp = dw + ((size_t)e * Fq + f0) * Dq + d0;
            ull acc[4][4];
#pragma unroll
            for (int q = 0; q < 4; q++)
#pragma unroll
                for (int p = 0; p < 4; p++) acc[q][p] = 0;
            for (int f4 = 0; f4 < 16; f4 += 4) {
                float4 w[4];
#pragma unroll
                for (int u = 0; u < 4; u++)
                    w[u] = *(const float4*)(wp + (size_t)(f4 + u) * Dq);
#pragma unroll
                for (int u = 0; u < 4; u++) {
                    ull wx = pack2(w[u].x, w[u].x);
                    ull wy = pack2(w[u].y, w[u].y);
                    ull wz = pack2(w[u].z, w[u].z);
                    ull ww = pack2(w[u].w, w[u].w);
#pragma unroll
                    for (int p = 0; p < 4; p++) {
                        ull t2 = s_vu[(f4 + u) * 4 + p];
                        FMA2(acc[0][p], t2, wx);
                        FMA2(acc[1][p], t2, wy);
                        FMA2(acc[2][p], t2, wz);
                        FMA2(acc[3][p], t2, ww);
                    }
                }
            }
#pragma unroll
            for (int q = 0; q < 4; q++)
#pragma unroll
                for (int p = 0; p < 4; p++) {
                    float lo, hi; unpack2(acc[q][p], lo, hi);
                    atomicAdd(&g_y[(size_t)(2 * p) * Dq + d0 + q], lo);
                    atomicAdd(&g_y[(size_t)(2 * p + 1) * Dq + d0 + q], hi);
                }
        }
    }
    grid_bar();

    // ============ Stage E: final rmsnorm + score head (8 blocks) ============
    if (blk < Bq) {
        int b = blk;
        float xr[4];
        float ssv[1]; ssv[0] = 0.f;
#pragma unroll
        for (int it = 0; it < 4; it++) {
            int d = tid + it * 256;
            xr[it] = hidden[(size_t)b * Sq * Dq + d] + g_attn[b * Dq + d] + g_y[b * Dq + d];
            ssv[0] += xr[it] * xr[it];
        }
        breduce<1>(ssv, s_red, s_out);
        if (tid == 0) s_rs[0] = rsqrtf(s_out[0] * (1.f / Dq) + EPSq);
        __syncthreads();
        float rs = s_rs[0];
        float p[2]; p[0] = 0.f; p[1] = 0.f;
#pragma unroll
        for (int it = 0; it < 4; it++) {
            int d = tid + it * 256;
            float xn = xr[it] * rs * flnw[d];
            p[0] = fmaf(xn, sw[d * 2 + 0], p[0]);
            p[1] = fmaf(xn, sw[d * 2 + 1], p[1]);
        }
        breduce<2>(p, s_red, s_out);
        if (tid == 0) {
            out[b * 2 + 0] = s_out[0];
            out[b * 2 + 1] = s_out[1];
        }
    }
}

// ---------------- launch ----------------
extern "C" void kernel_launch(void* const* d_in, const int* in_sizes, int n_in,
                              void* d_out, int out_size) {
    (void)in_sizes; (void)n_in; (void)out_size;
    const float* hidden = (const float*)d_in[0];
    const float* ln1w   = (const float*)d_in[1];
    // d_in[2]=q_w, d_in[3]=k_w: provably unused (causal token-0 softmax == 1)
    const float* vw     = (const float*)d_in[4];
    const float* ow     = (const float*)d_in[5];
    const float* ln2w   = (const float*)d_in[6];
    const float* rw     = (const float*)d_in[7];
    const float* gw     = (const float*)d_in[8];
    const float* uw     = (const float*)d_in[9];
    const float* dw     = (const float*)d_in[10];
    const float* flnw   = (const float*)d_in[11];
    const float* sw     = (const float*)d_in[12];
    float* out = (float*)d_out;

    fused_all<<<NB, NT>>>(hidden, ln1w, vw, ow, ln2w, rw, gw, uw, dw, flnw, sw, out);
}

// round 6
// speedup vs baseline: 1.7323x; 1.7323x over previous
#include <cuda_runtime.h>
#include <math.h>

#define Bq 8
#define Sq 1024
#define Dq 1024
#define Fq 3584
#define Eq 2
#define NB 256
#define NT 448
#define NW 14
#define EPSq 1e-6f

typedef unsigned long long ull;

// ---------------- device scratch (no allocation) ----------------
__device__ ull   g_pvu[64 * 4 * Dq];        // v0 partials [ic*4+p][j] (b-pairs)
__device__ float g_attn[Bq * Dq];           // attn output (atomic)
__device__ float g_accg[Eq * Bq * Fq];      // gate acc (atomic)
__device__ float g_accu[Eq * Bq * Fq];      // up acc (atomic)
__device__ float g_y[Bq * Dq];              // moe output (atomic)
__device__ unsigned g_barc = 0;
__device__ unsigned g_barg = 0;

// ---------------- f32x2 helpers ----------------
__device__ __forceinline__ ull pack2(float lo, float hi) {
    ull r;
    asm("mov.b64 %0, {%1, %2};" : "=l"(r) : "r"(__float_as_uint(lo)), "r"(__float_as_uint(hi)));
    return r;
}
__device__ __forceinline__ void unpack2(ull v, float& lo, float& hi) {
    unsigned a, b;
    asm("mov.b64 {%0, %1}, %2;" : "=r"(a), "=r"(b) : "l"(v));
    lo = __uint_as_float(a); hi = __uint_as_float(b);
}
#define FMA2(d, a, b) asm("fma.rn.f32x2 %0, %1, %2, %0;" : "+l"(d) : "l"(a), "l"(b))
#define ADD2(d, a)    asm("add.rn.f32x2 %0, %0, %1;"     : "+l"(d) : "l"(a))

// ---------------- software grid barrier ----------------
__device__ __forceinline__ void grid_bar() {
    __syncthreads();
    if (threadIdx.x == 0) {
        __threadfence();
        unsigned old = *(volatile unsigned*)&g_barg;
        if (atomicAdd(&g_barc, 1u) == (unsigned)gridDim.x - 1u) {
            g_barc = 0;
            __threadfence();
            atomicExch(&g_barg, old + 1u);
        } else {
            while (*(volatile unsigned*)&g_barg == old) __nanosleep(64);
        }
        __threadfence();
    }
    __syncthreads();
}

// ---------------- multi-value block reduction (14 warps) ----------
template <int NV>
__device__ __forceinline__ void breduce(const float* v, float* s_red, float* s_out) {
    int lane = threadIdx.x & 31, w = threadIdx.x >> 5;
#pragma unroll
    for (int k = 0; k < NV; k++) {
        float x = v[k];
#pragma unroll
        for (int o = 16; o; o >>= 1) x += __shfl_xor_sync(0xffffffffu, x, o);
        if (lane == 0) s_red[k * NW + w] = x;
    }
    __syncthreads();
    if (threadIdx.x < NV) {
        float s = 0.f;
#pragma unroll
        for (int j = 0; j < NW; j++) s += s_red[threadIdx.x * NW + j];
        s_out[threadIdx.x] = s;
    }
    __syncthreads();
}

__global__ void __launch_bounds__(NT, 2) fused_all(
    const float* __restrict__ hidden, const float* __restrict__ ln1w,
    const float* __restrict__ vw, const float* __restrict__ ow,
    const float* __restrict__ ln2w, const float* __restrict__ rw,
    const float* __restrict__ gw, const float* __restrict__ uw,
    const float* __restrict__ dw, const float* __restrict__ flnw,
    const float* __restrict__ sw, float* __restrict__ out)
{
    __shared__ float s_ht[Dq * Bq];   // 32KB: h2 [d][b]; C2 combine buf; D t-vec
    __shared__ float s_v[16 * Bq];    // v0 chunk in B
    __shared__ float s_red[16 * NW];
    __shared__ float s_out[16];
    __shared__ float s_rs[Bq];
    __shared__ int   s_sel[Bq];
    __shared__ float s_tw[Bq];

    const int tid = threadIdx.x;
    const int blk = blockIdx.x;
    ull* s_htu = (ull*)s_ht;
    ull* s_vu  = (ull*)s_v;

    // ============ Stage A0: zero atomic accumulators ============
    for (int idx = blk * NT + tid; idx < Eq * Bq * Fq; idx += NB * NT) {
        g_accg[idx] = 0.f; g_accu[idx] = 0.f;
    }
    for (int idx = blk * NT + tid; idx < Bq * Dq; idx += NB * NT) {
        g_attn[idx] = 0.f; g_y[idx] = 0.f;
    }

    // ============ A1: redundant h1 = rmsnorm(x0)*ln1_w -> s_ht[d][b] ============
    {
        float ss[Bq];
#pragma unroll
        for (int b = 0; b < Bq; b++) ss[b] = 0.f;
        for (int d = tid; d < Dq; d += NT) {
#pragma unroll
            for (int b = 0; b < Bq; b++) {
                float v = hidden[(size_t)b * Sq * Dq + d];
                ss[b] += v * v;
            }
        }
        breduce<Bq>(ss, s_red, s_out);
        if (tid < Bq) s_rs[tid] = rsqrtf(s_out[tid] * (1.f / Dq) + EPSq);
        __syncthreads();
        for (int d = tid; d < Dq; d += NT) {
            float lw = ln1w[d];
#pragma unroll
            for (int b = 0; b < Bq; b++)
                s_ht[d * Bq + b] = hidden[(size_t)b * Sq * Dq + d] * s_rs[b] * lw;
        }
        __syncthreads();
    }

    // ============ A2: v0 partials. 256 tasks: 64 ic(16) x 4 jc(256) ============
    if (tid < 256) {
        int ic = blk >> 2, jc = blk & 3;
        int j = jc * 256 + tid, ib = ic * 16;
        float w[16];
#pragma unroll
        for (int u = 0; u < 16; u++) w[u] = vw[(size_t)(ib + u) * Dq + j];
        ull acc[4] = {0, 0, 0, 0};
#pragma unroll
        for (int u = 0; u < 16; u++) {
            ull w2 = pack2(w[u], w[u]);
#pragma unroll
            for (int p = 0; p < 4; p++) FMA2(acc[p], s_htu[(ib + u) * 4 + p], w2);
        }
#pragma unroll
        for (int p = 0; p < 4; p++) g_pvu[(size_t)((blk >> 2) * 4 + p) * Dq + j] = acc[p];
    }
    grid_bar();

    // ============ Stage B: attn = v0 @ o_w ============
    {
        int ic = blk >> 2, jc = blk & 3;
        int ib = ic * 16;
        if (tid < 64) {
            int i = tid >> 2, p = tid & 3;
            ull s = 0;
#pragma unroll 8
            for (int c = 0; c < 64; c++) {
                ull v = g_pvu[(size_t)(c * 4 + p) * Dq + ib + i];
                ADD2(s, v);
            }
            s_vu[i * 4 + p] = s;
        }
        __syncthreads();
        if (tid < 256) {
            int j = jc * 256 + tid;
            float w[16];
#pragma unroll
            for (int u = 0; u < 16; u++) w[u] = ow[(size_t)(ib + u) * Dq + j];
            ull acc[4] = {0, 0, 0, 0};
#pragma unroll
            for (int u = 0; u < 16; u++) {
                ull w2 = pack2(w[u], w[u]);
#pragma unroll
                for (int p = 0; p < 4; p++) FMA2(acc[p], s_vu[u * 4 + p], w2);
            }
#pragma unroll
            for (int p = 0; p < 4; p++) {
                float lo, hi; unpack2(acc[p], lo, hi);
                atomicAdd(&g_attn[(2 * p) * Dq + j], lo);
                atomicAdd(&g_attn[(2 * p + 1) * Dq + j], hi);
            }
        }
    }
    grid_bar();

    // ============ C1: xmid -> h2 (s_ht) + router ============
    {
        __syncthreads();
        float ss[Bq];
#pragma unroll
        for (int b = 0; b < Bq; b++) ss[b] = 0.f;
        for (int d = tid; d < Dq; d += NT) {
#pragma unroll
            for (int b = 0; b < Bq; b++) {
                float v = hidden[(size_t)b * Sq * Dq + d] + g_attn[b * Dq + d];
                ss[b] += v * v;
            }
        }
        breduce<Bq>(ss, s_red, s_out);
        if (tid < Bq) s_rs[tid] = rsqrtf(s_out[tid] * (1.f / Dq) + EPSq);
        __syncthreads();
        float l[16];
#pragma unroll
        for (int k = 0; k < 16; k++) l[k] = 0.f;
        for (int d = tid; d < Dq; d += NT) {
            float r0 = rw[d * 2 + 0], r1 = rw[d * 2 + 1], w2d = ln2w[d];
#pragma unroll
            for (int b = 0; b < Bq; b++) {
                float xm = hidden[(size_t)b * Sq * Dq + d] + g_attn[b * Dq + d];
                float h2 = xm * s_rs[b] * w2d;
                s_ht[d * Bq + b] = h2;
                l[b]     = fmaf(h2, r0, l[b]);
                l[8 + b] = fmaf(h2, r1, l[8 + b]);
            }
        }
        breduce<16>(l, s_red, s_out);
        if (tid < Bq) {
            float l0 = s_out[tid], l1 = s_out[8 + tid];
            s_sel[tid] = (l1 > l0) ? 1 : 0;
            s_tw[tid]  = 1.f / (1.f + expf(-fabsf(l0 - l1)));
        }
        __syncthreads();
    }

    bool usedE[Eq];
#pragma unroll
    for (int e = 0; e < Eq; e++) {
        bool u = false;
#pragma unroll
        for (int b = 0; b < Bq; b++) u |= (s_sel[b] == e);
        usedE[e] = u;
    }

    // ==== C2: gate+up. 256 tasks: e x 8 ic(128) x 16 fc(224); i split in halves ====
    {
        int e = blk >> 7, r = blk & 127, ic = r >> 4, fc = r & 15;
        if (usedE[e]) {
            int half = tid / 224;       // 0 or 1
            int fl   = tid % 224;
            int f    = fc * 224 + fl;
            int ib   = ic * 128 + half * 64;
            const float* gp = gw + (size_t)e * Dq * Fq + f;
            const float* upp = uw + (size_t)e * Dq * Fq + f;
            ull ag[4] = {0, 0, 0, 0}, au[4] = {0, 0, 0, 0};
            for (int i8 = 0; i8 < 64; i8 += 8) {
                int i = ib + i8;
                float wg[8], wu[8];
#pragma unroll
                for (int u = 0; u < 8; u++) wg[u] = gp[(size_t)(i + u) * Fq];
#pragma unroll
                for (int u = 0; u < 8; u++) wu[u] = upp[(size_t)(i + u) * Fq];
#pragma unroll
                for (int u = 0; u < 8; u++) {
                    ull wg2 = pack2(wg[u], wg[u]);
                    ull wu2 = pack2(wu[u], wu[u]);
#pragma unroll
                    for (int p = 0; p < 4; p++) {
                        ull h2 = s_htu[(i + u) * 4 + p];
                        FMA2(ag[p], h2, wg2);
                        FMA2(au[p], h2, wu2);
                    }
                }
            }
            __syncthreads();            // all h2 reads done; reuse s_ht as combine buf
            ull* comb = s_htu;
            if (half == 1) {
#pragma unroll
                for (int q = 0; q < 4; q++) { comb[fl * 8 + q] = ag[q]; comb[fl * 8 + 4 + q] = au[q]; }
            }
            __syncthreads();
            if (half == 0) {
#pragma unroll
                for (int q = 0; q < 4; q++) { ADD2(ag[q], comb[fl * 8 + q]); ADD2(au[q], comb[fl * 8 + 4 + q]); }
#pragma unroll
                for (int p = 0; p < 4; p++) {
                    float lo, hi;
                    unpack2(ag[p], lo, hi);
                    atomicAdd(&g_accg[((size_t)e * Bq + 2 * p) * Fq + f], lo);
                    atomicAdd(&g_accg[((size_t)e * Bq + 2 * p + 1) * Fq + f], hi);
                    unpack2(au[p], lo, hi);
                    atomicAdd(&g_accu[((size_t)e * Bq + 2 * p) * Fq + f], lo);
                    atomicAdd(&g_accu[((size_t)e * Bq + 2 * p + 1) * Fq + f], hi);
                }
            }
        }
    }
    grid_bar();

    // ==== D: silu/mask + down. 256 tasks: e x 32 fc(112 rows) x 4 dc(256) ====
    {
        int e = blk >> 7, r = blk & 127, fc = r >> 2, dc = r & 3;
        if (usedE[e]) {
            int f0 = fc * 112;
            __syncthreads();
            for (int idx = tid; idx < 896; idx += NT) {   // t [fl][b] -> s_ht
                int fl = idx >> 3, b = idx & 7;
                float tv = 0.f;
                if (s_sel[b] == e) {
                    int f = f0 + fl;
                    float gg = g_accg[((size_t)e * Bq + b) * Fq + f];
                    float uu = g_accu[((size_t)e * Bq + b) * Fq + f];
                    tv = s_tw[b] * gg * (1.f / (1.f + expf(-gg))) * uu;
                }
                s_ht[fl * 8 + b] = tv;
            }
            __syncthreads();
            if (tid < 256) {
                int d = dc * 256 + tid;
                const float* dp = dw + ((size_t)e * Fq + f0) * Dq + d;
                ull acc[4] = {0, 0, 0, 0};
                for (int f16 = 0; f16 < 112; f16 += 16) {
                    float w[16];
#pragma unroll
                    for (int u = 0; u < 16; u++) w[u] = dp[(size_t)(f16 + u) * Dq];
#pragma unroll
                    for (int u = 0; u < 16; u++) {
                        ull w2 = pack2(w[u], w[u]);
#pragma unroll
                        for (int p = 0; p < 4; p++) FMA2(acc[p], s_htu[(f16 + u) * 4 + p], w2);
                    }
                }
#pragma unroll
                for (int p = 0; p < 4; p++) {
                    float lo, hi; unpack2(acc[p], lo, hi);
                    atomicAdd(&g_y[(2 * p) * Dq + d], lo);
                    atomicAdd(&g_y[(2 * p + 1) * Dq + d], hi);
                }
            }
        }
    }
    grid_bar();

    // ============ E: final rmsnorm + score head (8 blocks) ============
    if (blk < Bq) {
        int b = blk;
        float ssv[1]; ssv[0] = 0.f;
        for (int d = tid; d < Dq; d += NT) {
            float v = hidden[(size_t)b * Sq * Dq + d] + g_attn[b * Dq + d] + g_y[b * Dq + d];
            ssv[0] += v * v;
        }
        breduce<1>(ssv, s_red, s_out);
        if (tid == 0) s_rs[0] = rsqrtf(s_out[0] * (1.f / Dq) + EPSq);
        __syncthreads();
        float rs = s_rs[0];
        float p[2]; p[0] = 0.f; p[1] = 0.f;
        for (int d = tid; d < Dq; d += NT) {
            float v = hidden[(size_t)b * Sq * Dq + d] + g_attn[b * Dq + d] + g_y[b * Dq + d];
            float xn = v * rs * flnw[d];
            p[0] = fmaf(xn, sw[d * 2 + 0], p[0]);
            p[1] = fmaf(xn, sw[d * 2 + 1], p[1]);
        }
        breduce<2>(p, s_red, s_out);
        if (tid == 0) {
            out[b * 2 + 0] = s_out[0];
            out[b * 2 + 1] = s_out[1];
        }
    }
}

// ---------------- launch ----------------
extern "C" void kernel_launch(void* const* d_in, const int* in_sizes, int n_in,
                              void* d_out, int out_size) {
    (void)in_sizes; (void)n_in; (void)out_size;
    const float* hidden = (const float*)d_in[0];
    const float* ln1w   = (const float*)d_in[1];
    // d_in[2]=q_w, d_in[3]=k_w: provably unused (causal token-0 softmax == 1)
    const float* vw     = (const float*)d_in[4];
    const float* ow     = (const float*)d_in[5];
    const float* ln2w   = (const float*)d_in[6];
    const float* rw     = (const float*)d_in[7];
    const float* gw     = (const float*)d_in[8];
    const float* uw     = (const float*)d_in[9];
    const float* dw     = (const float*)d_in[10];
    const float* flnw   = (const float*)d_in[11];
    const float* sw     = (const float*)d_in[12];
    float* out = (float*)d_out;

    fused_all<<<NB, NT>>>(hidden, ln1w, vw, ow, ln2w, rw, gw, uw, dw, flnw, sw, out);
}